// round 10
// baseline (speedup 1.0000x reference)
#include <cuda_runtime.h>
#include <cstdint>

#define NN 200000
#define EE 8192
#define HH 64
#define EAA 32
#define AA 50
#define DF 128

#define NBLK 148
#define NTHR 512
#define NWARP (NTHR / 32)
#define TOTWARP (NBLK * NWARP)
#define NPAIR (EE / 2)

typedef unsigned long long u64;

// ---- persist shared memory layout (floats) ----
#define WMT_STRIDE 196
#define OFF_WMT 0
#define SZ_WMT (64 * WMT_STRIDE)            // 12544 (W_msg transposed, padded stride)
#define OFF_WIH (OFF_WMT + SZ_WMT)          // 12544
#define OFF_WHH (OFF_WIH + 16384)           // 28928
#define OFF_BM  (OFF_WHH + 16384)           // 45312
#define OFF_BL  (OFF_BM + 64)               // 45376
#define OFF_TW  (OFF_BL + 256)              // 45632
#define OFF_TB  (OFF_TW + 32)               // 45664
#define OFF_FEAT (OFF_TB + 32)              // 45696  (NWARP*384: two feature slots)
#define OFF_M   (OFF_FEAT + NWARP * 384)    // 51840  (NWARP*256: 4 message rows)
#define SMEM_FLOATS (OFF_M + NWARP * 256)   // 55936
#define SMEM_BYTES (SMEM_FLOATS * 4)        // 223744 (< 232448 cap)

// ---- device scratch ----
__device__ float g_h[(size_t)NN * HH];
__device__ float g_c[(size_t)NN * HH];
__device__ int   g_done[EE];
__device__ int   g_prev_s[EE];
__device__ int   g_prev_d[EE];
__device__ int   g_head[NN];
__device__ int   g_next[2 * EE];
__device__ float g_Wc[192 * AA];
__device__ float g_bc[AA];
__device__ unsigned g_bar_cnt;
__device__ volatile unsigned g_bar_gen;

// ---- f32x2 packed math (Blackwell FFMA2; ptxas never auto-fuses this) ----
__device__ __forceinline__ u64 fma2(u64 a, u64 b, u64 c) {
    u64 d;
    asm("fma.rn.f32x2 %0, %1, %2, %3;" : "=l"(d) : "l"(a), "l"(b), "l"(c));
    return d;
}
__device__ __forceinline__ u64 pack2(float lo, float hi) {
    u64 r;
    asm("mov.b64 %0, {%1, %2};" : "=l"(r) : "f"(lo), "f"(hi));
    return r;
}
__device__ __forceinline__ float2 unpack2(u64 v) {
    float2 f;
    asm("mov.b64 {%0, %1}, %2;" : "=f"(f.x), "=f"(f.y) : "l"(v));
    return f;
}

__device__ __forceinline__ void grid_bar() {
    __syncthreads();
    if (threadIdx.x == 0) {
        __threadfence();
        unsigned gen = g_bar_gen;
        if (atomicAdd(&g_bar_cnt, 1u) == (unsigned)(gridDim.x - 1u)) {
            g_bar_cnt = 0u;
            __threadfence();
            g_bar_gen = gen + 1u;
        } else {
            while (g_bar_gen == gen) __nanosleep(128);
            __threadfence();
        }
    }
    __syncthreads();
}

__device__ __forceinline__ float sigf(float v) { return 1.0f / (1.0f + __expf(-v)); }
__device__ __forceinline__ float tanhf_(float v) {
    float e = __expf(2.0f * v);
    return 1.0f - 2.0f / (e + 1.0f);
}

#define MFMA(acc, f, w)                      \
    acc = fma2((f).x, (w).x, acc);           \
    acc = fma2((f).y, (w).y, acc);

// 4 packed-accumulator FMAs: one multiplier against one weight pair (wa,wb)
#define ROW4(ACC, mp, wa, wb)                             \
    ACC[0] = fma2(mp, (wa).x, ACC[0]);                    \
    ACC[1] = fma2(mp, (wa).y, ACC[1]);                    \
    ACC[2] = fma2(mp, (wb).x, ACC[2]);                    \
    ACC[3] = fma2(mp, (wb).y, ACC[3]);

// LSTM epilogue for ONE event (no fence — caller publishes once per pair).
__device__ __forceinline__ void lstm_epi(const u64* R0, const u64* R1, int s, int d, int lane) {
    float acc0[8], acc1[8];
#pragma unroll
    for (int j = 0; j < 4; j++) {
        float2 pa = unpack2(R0[j]), pb = unpack2(R1[j]);
        acc0[2 * j] = pa.x; acc0[2 * j + 1] = pa.y;
        acc1[2 * j] = pb.x; acc1[2 * j + 1] = pb.y;
    }
    float f0g[4], o0g[4], f1g[4], o1g[4];
#pragma unroll
    for (int c2 = 0; c2 < 4; c2++) {
        f0g[c2] = __shfl_down_sync(0xffffffffu, acc0[c2], 16);
        o0g[c2] = __shfl_down_sync(0xffffffffu, acc0[4 + c2], 16);
        f1g[c2] = __shfl_down_sync(0xffffffffu, acc1[c2], 16);
        o1g[c2] = __shfl_down_sync(0xffffffffu, acc1[4 + c2], 16);
    }
    if (lane < 16) {
        float4 c0 = *(const float4*)(g_c + (size_t)s * HH + 4 * lane);
        float4 c1 = *(const float4*)(g_c + (size_t)d * HH + 4 * lane);
        float c0a[4] = {c0.x, c0.y, c0.z, c0.w};
        float c1a[4] = {c1.x, c1.y, c1.z, c1.w};
        float cn0[4], hn0[4], cn1[4], hn1[4];
#pragma unroll
        for (int c2 = 0; c2 < 4; c2++) {
            cn0[c2] = sigf(f0g[c2]) * c0a[c2] + sigf(acc0[c2]) * tanhf_(acc0[4 + c2]);
            hn0[c2] = sigf(o0g[c2]) * tanhf_(cn0[c2]);
            cn1[c2] = sigf(f1g[c2]) * c1a[c2] + sigf(acc1[c2]) * tanhf_(acc1[4 + c2]);
            hn1[c2] = sigf(o1g[c2]) * tanhf_(cn1[c2]);
        }
        if (s != d) {  // src==dst: dst (row 1) update wins, matching scatter order
            *(float4*)(g_h + (size_t)s * HH + 4 * lane) = make_float4(hn0[0], hn0[1], hn0[2], hn0[3]);
            *(float4*)(g_c + (size_t)s * HH + 4 * lane) = make_float4(cn0[0], cn0[1], cn0[2], cn0[3]);
        }
        *(float4*)(g_h + (size_t)d * HH + 4 * lane) = make_float4(hn1[0], hn1[1], hn1[2], hn1[3]);
        *(float4*)(g_c + (size_t)d * HH + 4 * lane) = make_float4(cn1[0], cn1[1], cn1[2], cn1[3]);
    }
}

// One event (DUAL=false) or two provably-independent events (DUAL=true) sharing
// every weight LDS. LSTM is SPLIT-PASS (W_ih then W_hh) to keep live regs ~56
// and avoid the R7/R9 spill failure. Normal L1 loads (acquire fence upstream).
template <bool DUAL>
__device__ __forceinline__ void run_events(
    int eA, int sA, int dA, int eB, int sB, int dB,
    float* sm, float* sFA, float* sFB, float* sMw, int lane,
    const float* __restrict__ eattr, const float* __restrict__ etime) {
    // ---- stage features: [0:64)=hs [64:128)=hd [128:160)=ea [160:192)=te ----
    {
        float twl = sm[OFF_TW + lane], tbl = sm[OFF_TB + lane];
        float tA = etime[eA];
        sFA[lane]       = g_h[(size_t)sA * HH + lane];
        sFA[32 + lane]  = g_h[(size_t)sA * HH + 32 + lane];
        sFA[64 + lane]  = g_h[(size_t)dA * HH + lane];
        sFA[96 + lane]  = g_h[(size_t)dA * HH + 32 + lane];
        sFA[128 + lane] = eattr[(size_t)eA * EAA + lane];
        sFA[160 + lane] = cosf(fmaf(tA, twl, tbl));
        if (DUAL) {
            float tB = etime[eB];
            sFB[lane]       = g_h[(size_t)sB * HH + lane];
            sFB[32 + lane]  = g_h[(size_t)sB * HH + 32 + lane];
            sFB[64 + lane]  = g_h[(size_t)dB * HH + lane];
            sFB[96 + lane]  = g_h[(size_t)dB * HH + 32 + lane];
            sFB[128 + lane] = eattr[(size_t)eB * EAA + lane];
            sFB[160 + lane] = cosf(fmaf(tB, twl, tbl));
        }
    }
    __syncwarp();

    // ---- message GEMV via f32x2; weights shared across up to 4 rows ----
    {
        const ulonglong2* w0p = (const ulonglong2*)(sm + OFF_WMT + lane * WMT_STRIDE);
        const ulonglong2* w1p = (const ulonglong2*)(sm + OFF_WMT + (lane + 32) * WMT_STRIDE);
        const ulonglong2* fA = (const ulonglong2*)sFA;
        const ulonglong2* fB = (const ulonglong2*)sFB;
        u64 a00 = pack2(sm[OFF_BM + lane], 0.0f);
        u64 a01 = pack2(sm[OFF_BM + 32 + lane], 0.0f);
        u64 a10 = a00, a11 = a01;
        u64 b00 = a00, b01 = a01, b10 = a00, b11 = a01;
#pragma unroll
        for (int q = 0; q < 16; q++) {  // k[0,64): row0 -> hd, row1 -> hs
            ulonglong2 w0 = w0p[q], w1 = w1p[q];
            ulonglong2 f0 = fA[16 + q], f1 = fA[q];
            MFMA(a00, f0, w0); MFMA(a01, f0, w1);
            MFMA(a10, f1, w0); MFMA(a11, f1, w1);
            if (DUAL) {
                ulonglong2 g0 = fB[16 + q], g1 = fB[q];
                MFMA(b00, g0, w0); MFMA(b01, g0, w1);
                MFMA(b10, g1, w0); MFMA(b11, g1, w1);
            }
        }
#pragma unroll
        for (int q = 16; q < 32; q++) {  // k[64,128): row0 -> hs, row1 -> hd
            ulonglong2 w0 = w0p[q], w1 = w1p[q];
            ulonglong2 f0 = fA[q - 16], f1 = fA[q];
            MFMA(a00, f0, w0); MFMA(a01, f0, w1);
            MFMA(a10, f1, w0); MFMA(a11, f1, w1);
            if (DUAL) {
                ulonglong2 g0 = fB[q - 16], g1 = fB[q];
                MFMA(b00, g0, w0); MFMA(b01, g0, w1);
                MFMA(b10, g1, w0); MFMA(b11, g1, w1);
            }
        }
#pragma unroll
        for (int q = 32; q < 48; q++) {  // k[128,192): shared ea/te per event
            ulonglong2 w0 = w0p[q], w1 = w1p[q];
            ulonglong2 f = fA[q];
            MFMA(a00, f, w0); MFMA(a01, f, w1);
            MFMA(a10, f, w0); MFMA(a11, f, w1);
            if (DUAL) {
                ulonglong2 g = fB[q];
                MFMA(b00, g, w0); MFMA(b01, g, w1);
                MFMA(b10, g, w0); MFMA(b11, g, w1);
            }
        }
        float2 p0 = unpack2(a00), p1 = unpack2(a01), p2 = unpack2(a10), p3 = unpack2(a11);
        sMw[lane]      = fmaxf(p0.x + p0.y, 0.0f);
        sMw[32 + lane] = fmaxf(p1.x + p1.y, 0.0f);
        sMw[64 + lane] = fmaxf(p2.x + p2.y, 0.0f);
        sMw[96 + lane] = fmaxf(p3.x + p3.y, 0.0f);
        if (DUAL) {
            float2 q0 = unpack2(b00), q1 = unpack2(b01), q2 = unpack2(b10), q3 = unpack2(b11);
            sMw[128 + lane] = fmaxf(q0.x + q0.y, 0.0f);
            sMw[160 + lane] = fmaxf(q1.x + q1.y, 0.0f);
            sMw[192 + lane] = fmaxf(q2.x + q2.y, 0.0f);
            sMw[224 + lane] = fmaxf(q3.x + q3.y, 0.0f);
        }
    }
    __syncwarp();

    // ---- LSTM gates: SPLIT-PASS to cap live registers ----
    {
        ulonglong2 bl_lo = *(const ulonglong2*)(sm + OFF_BL + 4 * lane);
        ulonglong2 bl_hi = *(const ulonglong2*)(sm + OFF_BL + 128 + 4 * lane);
        u64 A0[4] = {bl_lo.x, bl_lo.y, bl_hi.x, bl_hi.y};
        u64 A1[4] = {bl_lo.x, bl_lo.y, bl_hi.x, bl_hi.y};
        u64 B0[4], B1[4];
        if (DUAL) {
#pragma unroll
            for (int j = 0; j < 4; j++) { B0[j] = A0[j]; B1[j] = A0[j]; }
        }
        // pass 1: g += m @ W_ih  (only wa,wb live)
        {
            const ulonglong2* wih2 = (const ulonglong2*)(sm + OFF_WIH);
#pragma unroll 4
            for (int k = 0; k < 64; k++) {
                ulonglong2 wa = wih2[(k << 6) + lane], wb = wih2[(k << 6) + 32 + lane];
                float m0A = sMw[k], m1A = sMw[64 + k];
                u64 m0p = pack2(m0A, m0A), m1p = pack2(m1A, m1A);
                ROW4(A0, m0p, wa, wb);
                ROW4(A1, m1p, wa, wb);
                if (DUAL) {
                    float m0B = sMw[128 + k], m1B = sMw[192 + k];
                    u64 n0p = pack2(m0B, m0B), n1p = pack2(m1B, m1B);
                    ROW4(B0, n0p, wa, wb);
                    ROW4(B1, n1p, wa, wb);
                }
            }
        }
        // pass 2: g += h @ W_hh  (only ua,ub live)
        {
            const ulonglong2* whh2 = (const ulonglong2*)(sm + OFF_WHH);
#pragma unroll 4
            for (int k = 0; k < 64; k++) {
                ulonglong2 ua = whh2[(k << 6) + lane], ub = whh2[(k << 6) + 32 + lane];
                float h0A = sFA[k], h1A = sFA[64 + k];
                u64 h0p = pack2(h0A, h0A), h1p = pack2(h1A, h1A);
                ROW4(A0, h0p, ua, ub);
                ROW4(A1, h1p, ua, ub);
                if (DUAL) {
                    float h0B = sFB[k], h1B = sFB[64 + k];
                    u64 g0p = pack2(h0B, h0B), g1p = pack2(h1B, h1B);
                    ROW4(B0, g0p, ua, ub);
                    ROW4(B1, g1p, ua, ub);
                }
            }
        }
        lstm_epi(A0, A1, sA, dA, lane);
        if (DUAL) lstm_epi(B0, B1, sB, dB, lane);
    }
}

// ---- init: node-chain heads, zero touched h/c, fuse W_emb@W_cls, reset flags ----
__global__ void __launch_bounds__(512) k_init(const int* __restrict__ ei,
                                              const float* __restrict__ Wemb,
                                              const float* __restrict__ bemb,
                                              const float* __restrict__ Wcls,
                                              const float* __restrict__ bcls) {
    int t = blockIdx.x * blockDim.x + threadIdx.x;  // 65536 threads
    if (t < 2 * EE) g_head[ei[t]] = -1;
    {   // 4 threads per endpoint zero h/c (dupes benign)
        int ep = t >> 2, part = t & 3;
        if (ep < 2 * EE) {
            int v = ei[ep];
            float4 z = make_float4(0.f, 0.f, 0.f, 0.f);
            float4* hp = (float4*)(g_h + (size_t)v * HH + part * 16);
            float4* cp = (float4*)(g_c + (size_t)v * HH + part * 16);
#pragma unroll
            for (int i = 0; i < 4; i++) { hp[i] = z; cp[i] = z; }
        }
    }
    if (t < EE) g_done[t] = 0;
    if (t < 192 * AA) {
        int k = t / AA, a = t - k * AA;
        float s = 0.0f;
        const float* wr = Wemb + k * HH;
#pragma unroll 8
        for (int j = 0; j < HH; j++) s = fmaf(wr[j], Wcls[j * AA + a], s);
        g_Wc[t] = s;
    }
    if (t < AA) {
        float s = bcls[t];
        for (int j = 0; j < HH; j++) s = fmaf(bemb[j], Wcls[j * AA + t], s);
        g_bc[t] = s;
    }
    if (t == 0) { g_bar_cnt = 0u; g_bar_gen = 0u; }
}

// ---- build per-node endpoint chains (unordered) ----
__global__ void __launch_bounds__(512) k_chain(const int* __restrict__ ei) {
    int t = blockIdx.x * blockDim.x + threadIdx.x;
    if (t < 2 * EE) g_next[t] = atomicExch(&g_head[ei[t]], t);
}

// ---- extract immediate predecessor per endpoint (chains are ~1 entry avg) ----
__global__ void __launch_bounds__(512) k_prevk(const int* __restrict__ ei) {
    int t = blockIdx.x * blockDim.x + threadIdx.x;
    if (t >= 2 * EE) return;
    int v = ei[t];
    int e = (t < EE) ? t : t - EE;
    int best = -1;
    for (int j = g_head[v]; j >= 0; j = g_next[j]) {
        int ev = (j < EE) ? j : j - EE;
        if (ev < e && ev > best) best = ev;
    }
    if (t < EE) g_prev_s[e] = best;
    else        g_prev_d[e] = best;
}

__device__ __forceinline__ void wait_preds(int p0, int p1, int p2, int p3, int lane,
                                           volatile int* vd) {
    if (lane == 0) {
        int spins = 0;
        while ((p0 >= 0 && !vd[p0]) || (p1 >= 0 && !vd[p1]) ||
               (p2 >= 0 && !vd[p2]) || (p3 >= 0 && !vd[p3])) {
            __nanosleep(40);
            if (++spins > 20000000) break;  // fail visibly, never hang
        }
    }
    __syncwarp();
}

// ---- persistent: dataflow over event pairs; fuse when provably independent ----
__global__ void __launch_bounds__(NTHR, 1) k_persist(
    const float* __restrict__ x, const int* __restrict__ ei, const float* __restrict__ eattr,
    const float* __restrict__ etime, const float* __restrict__ tw, const float* __restrict__ tb,
    const float* __restrict__ Wmsg, const float* __restrict__ bmsg,
    const float* __restrict__ Wih, const float* __restrict__ Whh,
    const float* __restrict__ blstm, float* __restrict__ out) {
    extern __shared__ float sm[];
    const int tid = threadIdx.x;
    const int lane = tid & 31;
    const int wid = tid >> 5;

    // stage weights (W_msg transposed, padded stride; conflict-free LDS.128)
    for (int i = tid; i < 192 * 64; i += NTHR) {
        int k = i >> 6, j = i & 63;
        sm[OFF_WMT + j * WMT_STRIDE + k] = Wmsg[i];
    }
    {
        float4* d1 = (float4*)(sm + OFF_WIH);
        float4* d2 = (float4*)(sm + OFF_WHH);
        const float4* s1 = (const float4*)Wih;
        const float4* s2 = (const float4*)Whh;
        for (int i = tid; i < 4096; i += NTHR) { d1[i] = s1[i]; d2[i] = s2[i]; }
    }
    for (int i = tid; i < 64; i += NTHR) sm[OFF_BM + i] = bmsg[i];
    for (int i = tid; i < 256; i += NTHR) sm[OFF_BL + i] = blstm[i];
    if (tid < 32) { sm[OFF_TW + tid] = tw[tid]; sm[OFF_TB + tid] = tb[tid]; }
    __syncthreads();

    const int gw = blockIdx.x * NWARP + wid;
    float* sFA = sm + OFF_FEAT + wid * 384;
    float* sFB = sFA + 192;
    float* sMw = sm + OFF_M + wid * 256;
    volatile int* vdone = (volatile int*)g_done;

    for (int p = gw; p < NPAIR; p += TOTWARP) {
        int eA = 2 * p, eB = 2 * p + 1;
        int sA = ei[eA], dA = ei[EE + eA];
        int sB = ei[eB], dB = ei[EE + eB];
        int pA0 = g_prev_s[eA], pA1 = g_prev_d[eA];
        int pB0 = g_prev_s[eB], pB1 = g_prev_d[eB];
        // Fusion legality: eB's dep cone lies in [0,eA) => eA not an ancestor of
        // eB AND node sets disjoint (a shared node would force a pred >= eA).
        bool fuse = (pB0 < eA) && (pB1 < eA);
        if (fuse) {
            wait_preds(pA0, pA1, pB0, pB1, lane, vdone);
            __threadfence();  // acquire: order after flags; drop stale L1 h/c lines
            run_events<true>(eA, sA, dA, eB, sB, dB, sm, sFA, sFB, sMw, lane, eattr, etime);
            if (lane < 16) __threadfence();  // publish both events' h/c
            __syncwarp();
            if (lane == 0) { vdone[eA] = 1; vdone[eB] = 1; }
            __syncwarp();
        } else {
            wait_preds(pA0, pA1, -1, -1, lane, vdone);
            __threadfence();
            run_events<false>(eA, sA, dA, eA, sA, dA, sm, sFA, sFB, sMw, lane, eattr, etime);
            if (lane < 16) __threadfence();
            __syncwarp();
            if (lane == 0) vdone[eA] = 1;
            __syncwarp();
            wait_preds(pB0, pB1, -1, -1, lane, vdone);
            __threadfence();
            run_events<false>(eB, sB, dB, eB, sB, dB, sm, sFA, sFB, sMw, lane, eattr, etime);
            if (lane < 16) __threadfence();
            __syncwarp();
            if (lane == 0) vdone[eB] = 1;
            __syncwarp();
        }
    }

    grid_bar();  // classifier needs FINAL h

    // ---- classifier: logits[e] = [h[dst] || x[dst]] @ Wc + bc ----
    for (int i = tid; i < 192 * AA; i += NTHR) sm[OFF_WMT + i] = g_Wc[i];
    for (int i = tid; i < AA; i += NTHR) sm[OFF_WMT + 9600 + i] = g_bc[i];
    __syncthreads();
    const float* sWc = sm + OFF_WMT;
    const float* sBc = sm + OFF_WMT + 9600;

    for (int e = gw; e < EE; e += TOTWARP) {
        int d = ei[EE + e];
        __syncwarp();
        sFA[lane]      = g_h[(size_t)d * HH + lane];
        sFA[32 + lane] = g_h[(size_t)d * HH + 32 + lane];
        {
            const float4* xv = (const float4*)(x + (size_t)d * DF);
            ((float4*)(sFA + 64))[lane] = xv[lane];
        }
        __syncwarp();
        float r0 = sBc[lane];
        float r1 = (lane < AA - 32) ? sBc[32 + lane] : 0.0f;
        const float4* fvc = (const float4*)sFA;
#pragma unroll 4
        for (int q = 0; q < 48; ++q) {
            float4 f = fvc[q];
            int kb = 4 * q;
            r0 = fmaf(f.x, sWc[(kb + 0) * AA + lane], r0);
            r0 = fmaf(f.y, sWc[(kb + 1) * AA + lane], r0);
            r0 = fmaf(f.z, sWc[(kb + 2) * AA + lane], r0);
            r0 = fmaf(f.w, sWc[(kb + 3) * AA + lane], r0);
            r1 = fmaf(f.x, sWc[(kb + 0) * AA + 32 + lane], r1);
            r1 = fmaf(f.y, sWc[(kb + 1) * AA + 32 + lane], r1);
            r1 = fmaf(f.z, sWc[(kb + 2) * AA + 32 + lane], r1);
            r1 = fmaf(f.w, sWc[(kb + 3) * AA + 32 + lane], r1);
        }
        float* op = out + (size_t)e * AA;
        op[lane] = r0;
        if (lane < AA - 32) op[32 + lane] = r1;
    }
}

extern "C" void kernel_launch(void* const* d_in, const int* in_sizes, int n_in,
                              void* d_out, int out_size) {
    const float* x     = (const float*)d_in[0];
    const int*   ei    = (const int*)d_in[1];
    const float* eattr = (const float*)d_in[2];
    const float* etime = (const float*)d_in[3];
    const float* tw    = (const float*)d_in[4];
    const float* tb    = (const float*)d_in[5];
    const float* Wmsg  = (const float*)d_in[6];
    const float* bmsg  = (const float*)d_in[7];
    const float* Wih   = (const float*)d_in[8];
    const float* Whh   = (const float*)d_in[9];
    const float* blstm = (const float*)d_in[10];
    const float* Wemb  = (const float*)d_in[11];
    const float* bemb  = (const float*)d_in[12];
    const float* Wcls  = (const float*)d_in[13];
    const float* bcls  = (const float*)d_in[14];
    float* out = (float*)d_out;

    cudaFuncSetAttribute(k_persist, cudaFuncAttributeMaxDynamicSharedMemorySize, SMEM_BYTES);

    k_init<<<128, 512>>>(ei, Wemb, bemb, Wcls, bcls);
    k_chain<<<32, 512>>>(ei);
    k_prevk<<<32, 512>>>(ei);
    k_persist<<<NBLK, NTHR, SMEM_BYTES>>>(x, ei, eattr, etime, tw, tb, Wmsg, bmsg, Wih, Whh,
                                          blstm, out);
}

// round 12
// speedup vs baseline: 1.6663x; 1.6663x over previous
#include <cuda_runtime.h>
#include <cstdint>

#define NN 200000
#define EE 8192
#define HH 64
#define EAA 32
#define AA 50
#define DF 128

#define NBLK 148
#define NTHR 512
#define NWARP (NTHR / 32)
#define TOTWARP (NBLK * NWARP)

typedef unsigned long long u64;

// ---- persist shared memory layout (floats) ----
#define WMT_STRIDE 196
#define OFF_WMT 0
#define SZ_WMT (64 * WMT_STRIDE)            // 12544 (W_msg transposed, padded stride)
#define OFF_WIH (OFF_WMT + SZ_WMT)          // 12544
#define OFF_WHH (OFF_WIH + 16384)           // 28928
#define OFF_BM  (OFF_WHH + 16384)           // 45312
#define OFF_BL  (OFF_BM + 64)               // 45376
#define OFF_TW  (OFF_BL + 256)              // 45632
#define OFF_TB  (OFF_TW + 32)               // 45664
#define OFF_FEAT (OFF_TB + 32)              // 45696  (NWARP*192: message features)
#define OFF_MD  (OFF_FEAT + NWARP * 192)    // 48768  (NWARP*256: duplicated m)
#define OFF_FD  (OFF_MD + NWARP * 256)      // 52864  (NWARP*256: duplicated h)
#define SMEM_FLOATS (OFF_FD + NWARP * 256)  // 56960
#define SMEM_BYTES (SMEM_FLOATS * 4)        // 227840 (< 232448 cap)

// ---- device scratch ----
__device__ float g_h[(size_t)NN * HH];
__device__ float g_c[(size_t)NN * HH];
__device__ int   g_done[EE];
__device__ int   g_prev_s[EE];
__device__ int   g_prev_d[EE];
__device__ int   g_succ_s[EE];
__device__ int   g_succ_d[EE];
__device__ int   g_head[NN];
__device__ int   g_next[2 * EE];
__device__ float g_Wc[192 * AA];
__device__ float g_bc[AA];
__device__ unsigned g_bar_cnt;
__device__ volatile unsigned g_bar_gen;

// ---- f32x2 packed math (Blackwell FFMA2; ptxas never auto-fuses this) ----
__device__ __forceinline__ u64 fma2(u64 a, u64 b, u64 c) {
    u64 d;
    asm("fma.rn.f32x2 %0, %1, %2, %3;" : "=l"(d) : "l"(a), "l"(b), "l"(c));
    return d;
}
__device__ __forceinline__ u64 pack2(float lo, float hi) {
    u64 r;
    asm("mov.b64 %0, {%1, %2};" : "=l"(r) : "f"(lo), "f"(hi));
    return r;
}
__device__ __forceinline__ float2 unpack2(u64 v) {
    float2 f;
    asm("mov.b64 {%0, %1}, %2;" : "=f"(f.x), "=f"(f.y) : "l"(v));
    return f;
}

__device__ __forceinline__ void grid_bar() {
    __syncthreads();
    if (threadIdx.x == 0) {
        __threadfence();
        unsigned gen = g_bar_gen;
        if (atomicAdd(&g_bar_cnt, 1u) == (unsigned)(gridDim.x - 1u)) {
            g_bar_cnt = 0u;
            __threadfence();
            g_bar_gen = gen + 1u;
        } else {
            while (g_bar_gen == gen) __nanosleep(128);
            __threadfence();
        }
    }
    __syncthreads();
}

__device__ __forceinline__ float sigf(float v) { return 1.0f / (1.0f + __expf(-v)); }
__device__ __forceinline__ float tanhf_(float v) {
    float e = __expf(2.0f * v);
    return 1.0f - 2.0f / (e + 1.0f);
}

#define MFMA(acc, f, w)                      \
    acc = fma2((f).x, (w).x, acc);           \
    acc = fma2((f).y, (w).y, acc);

// 4 packed-accumulator FMAs: one packed multiplier against weight pair (wa,wb)
#define ROW4(ACC, mp, wa, wb)                             \
    ACC[0] = fma2(mp, (wa).x, ACC[0]);                    \
    ACC[1] = fma2(mp, (wa).y, ACC[1]);                    \
    ACC[2] = fma2(mp, (wb).x, ACC[2]);                    \
    ACC[3] = fma2(mp, (wb).y, ACC[3]);

// ---- init: node-chain heads, zero touched h/c, fuse W_emb@W_cls, reset flags ----
__global__ void __launch_bounds__(512) k_init(const int* __restrict__ ei,
                                              const float* __restrict__ Wemb,
                                              const float* __restrict__ bemb,
                                              const float* __restrict__ Wcls,
                                              const float* __restrict__ bcls) {
    int t = blockIdx.x * blockDim.x + threadIdx.x;  // 65536 threads
    if (t < 2 * EE) g_head[ei[t]] = -1;
    {   // 4 threads per endpoint zero h/c (dupes benign)
        int ep = t >> 2, part = t & 3;
        if (ep < 2 * EE) {
            int v = ei[ep];
            float4 z = make_float4(0.f, 0.f, 0.f, 0.f);
            float4* hp = (float4*)(g_h + (size_t)v * HH + part * 16);
            float4* cp = (float4*)(g_c + (size_t)v * HH + part * 16);
#pragma unroll
            for (int i = 0; i < 4; i++) { hp[i] = z; cp[i] = z; }
        }
    }
    if (t < EE) g_done[t] = 0;
    if (t < 192 * AA) {
        int k = t / AA, a = t - k * AA;
        float s = 0.0f;
        const float* wr = Wemb + k * HH;
#pragma unroll 8
        for (int j = 0; j < HH; j++) s = fmaf(wr[j], Wcls[j * AA + a], s);
        g_Wc[t] = s;
    }
    if (t < AA) {
        float s = bcls[t];
        for (int j = 0; j < HH; j++) s = fmaf(bemb[j], Wcls[j * AA + t], s);
        g_bc[t] = s;
    }
    if (t == 0) { g_bar_cnt = 0u; g_bar_gen = 0u; }
}

// ---- build per-node endpoint chains (unordered) ----
__global__ void __launch_bounds__(512) k_chain(const int* __restrict__ ei) {
    int t = blockIdx.x * blockDim.x + threadIdx.x;
    if (t < 2 * EE) g_next[t] = atomicExch(&g_head[ei[t]], t);
}

// ---- per endpoint: immediate predecessor event + "has successor" flag ----
__global__ void __launch_bounds__(512) k_prevk(const int* __restrict__ ei) {
    int t = blockIdx.x * blockDim.x + threadIdx.x;
    if (t >= 2 * EE) return;
    int v = ei[t];
    int e = (t < EE) ? t : t - EE;
    int best = -1;
    int succ = 0;
    for (int j = g_head[v]; j >= 0; j = g_next[j]) {
        int ev = (j < EE) ? j : j - EE;
        if (ev < e && ev > best) best = ev;
        if (ev > e) succ = 1;
    }
    if (t < EE) { g_prev_s[e] = best; g_succ_s[e] = succ; }
    else        { g_prev_d[e] = best; g_succ_d[e] = succ; }
}

// ---- persistent: dataflow singles; fences only on dependent/depended events ----
__global__ void __launch_bounds__(NTHR, 1) k_persist(
    const float* __restrict__ x, const int* __restrict__ ei, const float* __restrict__ eattr,
    const float* __restrict__ etime, const float* __restrict__ tw, const float* __restrict__ tb,
    const float* __restrict__ Wmsg, const float* __restrict__ bmsg,
    const float* __restrict__ Wih, const float* __restrict__ Whh,
    const float* __restrict__ blstm, float* __restrict__ out) {
    extern __shared__ float sm[];
    const int tid = threadIdx.x;
    const int lane = tid & 31;
    const int wid = tid >> 5;

    // stage weights (W_msg transposed, padded stride; conflict-free LDS.128)
    for (int i = tid; i < 192 * 64; i += NTHR) {
        int k = i >> 6, j = i & 63;
        sm[OFF_WMT + j * WMT_STRIDE + k] = Wmsg[i];
    }
    {
        float4* d1 = (float4*)(sm + OFF_WIH);
        float4* d2 = (float4*)(sm + OFF_WHH);
        const float4* s1 = (const float4*)Wih;
        const float4* s2 = (const float4*)Whh;
        for (int i = tid; i < 4096; i += NTHR) { d1[i] = s1[i]; d2[i] = s2[i]; }
    }
    for (int i = tid; i < 64; i += NTHR) sm[OFF_BM + i] = bmsg[i];
    for (int i = tid; i < 256; i += NTHR) sm[OFF_BL + i] = blstm[i];
    if (tid < 32) { sm[OFF_TW + tid] = tw[tid]; sm[OFF_TB + tid] = tb[tid]; }
    __syncthreads();

    const int gw = blockIdx.x * NWARP + wid;
    float* sF = sm + OFF_FEAT + wid * 192;
    float2* md = (float2*)(sm + OFF_MD + wid * 256);   // duplicated m, 128 pairs
    float2* fd = (float2*)(sm + OFF_FD + wid * 256);   // duplicated h, 128 pairs
    volatile int* vdone = (volatile int*)g_done;

    for (int e = gw; e < EE; e += TOTWARP) {
        int s = ei[e], d = ei[EE + e];
        int ps = g_prev_s[e], pd = g_prev_d[e];
        const bool haspred = (ps >= 0) || (pd >= 0);
        if (haspred) {
            if (lane == 0) {
                int spins = 0;
                while ((ps >= 0 && vdone[ps] == 0) || (pd >= 0 && vdone[pd] == 0)) {
                    __nanosleep(40);
                    if (++spins > 20000000) break;  // fail visibly, never hang
                }
            }
            __syncwarp();
            __threadfence();  // acquire: order after flags; drop stale L1 h/c lines
        }

        // ---- stage features: sF=[hs|hd|ea|te]; fd = duplicated (h,h) pairs ----
        {
            float t = etime[e];
            float v0 = g_h[(size_t)s * HH + lane];
            float v1 = g_h[(size_t)s * HH + 32 + lane];
            float v2 = g_h[(size_t)d * HH + lane];
            float v3 = g_h[(size_t)d * HH + 32 + lane];
            sF[lane] = v0; sF[32 + lane] = v1; sF[64 + lane] = v2; sF[96 + lane] = v3;
            sF[128 + lane] = eattr[(size_t)e * EAA + lane];
            sF[160 + lane] = cosf(fmaf(t, sm[OFF_TW + lane], sm[OFF_TB + lane]));
            fd[lane]      = make_float2(v0, v0);
            fd[32 + lane] = make_float2(v1, v1);
            fd[64 + lane] = make_float2(v2, v2);
            fd[96 + lane] = make_float2(v3, v3);
        }
        __syncwarp();

        // ---- message GEMV via f32x2 (unchanged from R6) ----
        {
            const ulonglong2* w0p = (const ulonglong2*)(sm + OFF_WMT + lane * WMT_STRIDE);
            const ulonglong2* w1p = (const ulonglong2*)(sm + OFF_WMT + (lane + 32) * WMT_STRIDE);
            const ulonglong2* fv = (const ulonglong2*)sF;
            u64 a00 = pack2(sm[OFF_BM + lane], 0.0f);
            u64 a01 = pack2(sm[OFF_BM + 32 + lane], 0.0f);
            u64 a10 = a00, a11 = a01;
#pragma unroll
            for (int q = 0; q < 16; q++) {  // k[0,64): row0 -> hd, row1 -> hs
                ulonglong2 w0 = w0p[q], w1 = w1p[q];
                ulonglong2 f0 = fv[16 + q], f1 = fv[q];
                MFMA(a00, f0, w0); MFMA(a01, f0, w1);
                MFMA(a10, f1, w0); MFMA(a11, f1, w1);
            }
#pragma unroll
            for (int q = 16; q < 32; q++) {  // k[64,128): row0 -> hs, row1 -> hd
                ulonglong2 w0 = w0p[q], w1 = w1p[q];
                ulonglong2 f0 = fv[q - 16], f1 = fv[q];
                MFMA(a00, f0, w0); MFMA(a01, f0, w1);
                MFMA(a10, f1, w0); MFMA(a11, f1, w1);
            }
#pragma unroll
            for (int q = 32; q < 48; q++) {  // k[128,192): shared ea/te
                ulonglong2 w0 = w0p[q], w1 = w1p[q];
                ulonglong2 f = fv[q];
                MFMA(a00, f, w0); MFMA(a01, f, w1);
                MFMA(a10, f, w0); MFMA(a11, f, w1);
            }
            float2 p0 = unpack2(a00), p1 = unpack2(a01), p2 = unpack2(a10), p3 = unpack2(a11);
            float r00 = fmaxf(p0.x + p0.y, 0.0f);
            float r01 = fmaxf(p1.x + p1.y, 0.0f);
            float r10 = fmaxf(p2.x + p2.y, 0.0f);
            float r11 = fmaxf(p3.x + p3.y, 0.0f);
            md[lane]      = make_float2(r00, r00);   // row0 m cols [0,32)
            md[32 + lane] = make_float2(r01, r01);   // row0 m cols [32,64)
            md[64 + lane] = make_float2(r10, r10);   // row1 m cols [0,32)
            md[96 + lane] = make_float2(r11, r11);   // row1 m cols [32,64)
        }
        __syncwarp();

        // ---- LSTM gates: split-pass, packed multipliers loaded directly ----
        float acc0[8], acc1[8];
        {
            ulonglong2 bl_lo = *(const ulonglong2*)(sm + OFF_BL + 4 * lane);
            ulonglong2 bl_hi = *(const ulonglong2*)(sm + OFF_BL + 128 + 4 * lane);
            u64 A0[4] = {bl_lo.x, bl_lo.y, bl_hi.x, bl_hi.y};  // row0 (src)
            u64 A1[4] = {bl_lo.x, bl_lo.y, bl_hi.x, bl_hi.y};  // row1 (dst)
            const u64* mdu = (const u64*)md;
            const u64* fdu = (const u64*)fd;
            // pass 1: g += m @ W_ih
            {
                const ulonglong2* wih2 = (const ulonglong2*)(sm + OFF_WIH);
#pragma unroll 8
                for (int k = 0; k < 64; k++) {
                    ulonglong2 wa = wih2[(k << 6) + lane], wb = wih2[(k << 6) + 32 + lane];
                    u64 m0p = mdu[k], m1p = mdu[64 + k];
                    ROW4(A0, m0p, wa, wb);
                    ROW4(A1, m1p, wa, wb);
                }
            }
            // pass 2: g += h @ W_hh
            {
                const ulonglong2* whh2 = (const ulonglong2*)(sm + OFF_WHH);
#pragma unroll 8
                for (int k = 0; k < 64; k++) {
                    ulonglong2 ua = whh2[(k << 6) + lane], ub = whh2[(k << 6) + 32 + lane];
                    u64 h0p = fdu[k], h1p = fdu[64 + k];
                    ROW4(A0, h0p, ua, ub);
                    ROW4(A1, h1p, ua, ub);
                }
            }
#pragma unroll
            for (int j = 0; j < 4; j++) {
                float2 pa = unpack2(A0[j]), pb = unpack2(A1[j]);
                acc0[2 * j] = pa.x; acc0[2 * j + 1] = pa.y;
                acc1[2 * j] = pb.x; acc1[2 * j + 1] = pb.y;
            }
        }

        // ---- epilogue: lanes 0..15 = i|g, lanes 16..31 = f|o ----
        const bool hassucc = (g_succ_s[e] | g_succ_d[e]) != 0;
        {
            float f0g[4], o0g[4], f1g[4], o1g[4];
#pragma unroll
            for (int c2 = 0; c2 < 4; c2++) {
                f0g[c2] = __shfl_down_sync(0xffffffffu, acc0[c2], 16);
                o0g[c2] = __shfl_down_sync(0xffffffffu, acc0[4 + c2], 16);
                f1g[c2] = __shfl_down_sync(0xffffffffu, acc1[c2], 16);
                o1g[c2] = __shfl_down_sync(0xffffffffu, acc1[4 + c2], 16);
            }
            if (lane < 16) {
                float4 c0 = *(const float4*)(g_c + (size_t)s * HH + 4 * lane);
                float4 c1 = *(const float4*)(g_c + (size_t)d * HH + 4 * lane);
                float c0a[4] = {c0.x, c0.y, c0.z, c0.w};
                float c1a[4] = {c1.x, c1.y, c1.z, c1.w};
                float cn0[4], hn0[4], cn1[4], hn1[4];
#pragma unroll
                for (int c2 = 0; c2 < 4; c2++) {
                    cn0[c2] = sigf(f0g[c2]) * c0a[c2] + sigf(acc0[c2]) * tanhf_(acc0[4 + c2]);
                    hn0[c2] = sigf(o0g[c2]) * tanhf_(cn0[c2]);
                    cn1[c2] = sigf(f1g[c2]) * c1a[c2] + sigf(acc1[c2]) * tanhf_(acc1[4 + c2]);
                    hn1[c2] = sigf(o1g[c2]) * tanhf_(cn1[c2]);
                }
                if (s != d) {  // src==dst: dst (row 1) update wins, matching scatter
                    *(float4*)(g_h + (size_t)s * HH + 4 * lane) = make_float4(hn0[0], hn0[1], hn0[2], hn0[3]);
                    *(float4*)(g_c + (size_t)s * HH + 4 * lane) = make_float4(cn0[0], cn0[1], cn0[2], cn0[3]);
                }
                *(float4*)(g_h + (size_t)d * HH + 4 * lane) = make_float4(hn1[0], hn1[1], hn1[2], hn1[3]);
                *(float4*)(g_c + (size_t)d * HH + 4 * lane) = make_float4(cn1[0], cn1[1], cn1[2], cn1[3]);
                if (hassucc) __threadfence();  // release: publish h/c before flag
            }
        }
        __syncwarp();
        if (hassucc && lane == 0) vdone[e] = 1;
        __syncwarp();
    }

    grid_bar();  // fences every thread: all h/c visible to classifier

    // ---- classifier: logits[e] = [h[dst] || x[dst]] @ Wc + bc ----
    for (int i = tid; i < 192 * AA; i += NTHR) sm[OFF_WMT + i] = g_Wc[i];
    for (int i = tid; i < AA; i += NTHR) sm[OFF_WMT + 9600 + i] = g_bc[i];
    __syncthreads();
    const float* sWc = sm + OFF_WMT;
    const float* sBc = sm + OFF_WMT + 9600;

    for (int e = gw; e < EE; e += TOTWARP) {
        int d = ei[EE + e];
        __syncwarp();
        sF[lane]      = g_h[(size_t)d * HH + lane];
        sF[32 + lane] = g_h[(size_t)d * HH + 32 + lane];
        {
            const float4* xv = (const float4*)(x + (size_t)d * DF);
            ((float4*)(sF + 64))[lane] = xv[lane];
        }
        __syncwarp();
        float r0 = sBc[lane];
        float r1 = (lane < AA - 32) ? sBc[32 + lane] : 0.0f;
        const float4* fvc = (const float4*)sF;
#pragma unroll 4
        for (int q = 0; q < 48; ++q) {
            float4 f = fvc[q];
            int kb = 4 * q;
            r0 = fmaf(f.x, sWc[(kb + 0) * AA + lane], r0);
            r0 = fmaf(f.y, sWc[(kb + 1) * AA + lane], r0);
            r0 = fmaf(f.z, sWc[(kb + 2) * AA + lane], r0);
            r0 = fmaf(f.w, sWc[(kb + 3) * AA + lane], r0);
            r1 = fmaf(f.x, sWc[(kb + 0) * AA + 32 + lane], r1);
            r1 = fmaf(f.y, sWc[(kb + 1) * AA + 32 + lane], r1);
            r1 = fmaf(f.z, sWc[(kb + 2) * AA + 32 + lane], r1);
            r1 = fmaf(f.w, sWc[(kb + 3) * AA + 32 + lane], r1);
        }
        float* op = out + (size_t)e * AA;
        op[lane] = r0;
        if (lane < AA - 32) op[32 + lane] = r1;
    }
}

extern "C" void kernel_launch(void* const* d_in, const int* in_sizes, int n_in,
                              void* d_out, int out_size) {
    const float* x     = (const float*)d_in[0];
    const int*   ei    = (const int*)d_in[1];
    const float* eattr = (const float*)d_in[2];
    const float* etime = (const float*)d_in[3];
    const float* tw    = (const float*)d_in[4];
    const float* tb    = (const float*)d_in[5];
    const float* Wmsg  = (const float*)d_in[6];
    const float* bmsg  = (const float*)d_in[7];
    const float* Wih   = (const float*)d_in[8];
    const float* Whh   = (const float*)d_in[9];
    const float* blstm = (const float*)d_in[10];
    const float* Wemb  = (const float*)d_in[11];
    const float* bemb  = (const float*)d_in[12];
    const float* Wcls  = (const float*)d_in[13];
    const float* bcls  = (const float*)d_in[14];
    float* out = (float*)d_out;

    cudaFuncSetAttribute(k_persist, cudaFuncAttributeMaxDynamicSharedMemorySize, SMEM_BYTES);

    k_init<<<128, 512>>>(ei, Wemb, bemb, Wcls, bcls);
    k_chain<<<32, 512>>>(ei);
    k_prevk<<<32, 512>>>(ei);
    k_persist<<<NBLK, NTHR, SMEM_BYTES>>>(x, ei, eattr, etime, tw, tb, Wmsg, bmsg, Wih, Whh,
                                          blstm, out);
}

// round 16
// speedup vs baseline: 1.7506x; 1.0506x over previous
#include <cuda_runtime.h>
#include <cstdint>

#define NN 200000
#define EE 8192
#define HH 64
#define EAA 32
#define AA 50
#define DF 128

#define NBLK 148
#define NTHR 512
#define NWARP (NTHR / 32)
#define TOTWARP (NBLK * NWARP)
#define NPAIR (EE / 2)

typedef unsigned long long u64;

// ---- persist shared memory layout (floats) ----
#define WMT_STRIDE 196
#define OFF_WMT 0
#define SZ_WMT (64 * WMT_STRIDE)            // 12544 (W_msg transposed, padded stride)
#define OFF_WIH (OFF_WMT + SZ_WMT)          // 12544
#define OFF_WHH (OFF_WIH + 16384)           // 28928
#define OFF_BM  (OFF_WHH + 16384)           // 45312
#define OFF_BL  (OFF_BM + 64)               // 45376
#define OFF_TW  (OFF_BL + 256)              // 45632
#define OFF_TB  (OFF_TW + 32)               // 45664
#define OFF_FEAT (OFF_TB + 32)              // 45696  (NWARP*384: sFA|sFB)
#define OFF_MW  (OFF_FEAT + NWARP * 384)    // 51840  (NWARP*256: messages A|B)
#define SMEM_FLOATS (OFF_MW + NWARP * 256)  // 55936
#define SMEM_BYTES (SMEM_FLOATS * 4)        // 223744 (< 232448 cap)

// ---- device scratch ----
__device__ float g_h[(size_t)NN * HH];
__device__ float g_c[(size_t)NN * HH];
__device__ int   g_done[EE];
__device__ int   g_prev_s[EE];
__device__ int   g_prev_d[EE];
__device__ int   g_succ_s[EE];
__device__ int   g_succ_d[EE];
__device__ int   g_head[NN];
__device__ int   g_next[2 * EE];
__device__ float g_Wc[192 * AA];
__device__ float g_bc[AA];
__device__ unsigned g_bar_cnt;
__device__ volatile unsigned g_bar_gen;

// ---- f32x2 packed math (Blackwell FFMA2; ptxas never auto-fuses this) ----
__device__ __forceinline__ u64 fma2(u64 a, u64 b, u64 c) {
    u64 d;
    asm("fma.rn.f32x2 %0, %1, %2, %3;" : "=l"(d) : "l"(a), "l"(b), "l"(c));
    return d;
}
__device__ __forceinline__ u64 pack2(float lo, float hi) {
    u64 r;
    asm("mov.b64 %0, {%1, %2};" : "=l"(r) : "f"(lo), "f"(hi));
    return r;
}
__device__ __forceinline__ float2 unpack2(u64 v) {
    float2 f;
    asm("mov.b64 {%0, %1}, %2;" : "=f"(f.x), "=f"(f.y) : "l"(v));
    return f;
}

__device__ __forceinline__ void grid_bar() {
    __syncthreads();
    if (threadIdx.x == 0) {
        __threadfence();
        unsigned gen = g_bar_gen;
        if (atomicAdd(&g_bar_cnt, 1u) == (unsigned)(gridDim.x - 1u)) {
            g_bar_cnt = 0u;
            __threadfence();
            g_bar_gen = gen + 1u;
        } else {
            while (g_bar_gen == gen) __nanosleep(128);
            __threadfence();
        }
    }
    __syncthreads();
}

__device__ __forceinline__ float sigf(float v) { return 1.0f / (1.0f + __expf(-v)); }
__device__ __forceinline__ float tanhf_(float v) {
    float e = __expf(2.0f * v);
    return 1.0f - 2.0f / (e + 1.0f);
}

#define MFMA(acc, f, w)                      \
    acc = fma2((f).x, (w).x, acc);           \
    acc = fma2((f).y, (w).y, acc);

// 4 packed-accumulator FMAs: one packed multiplier against weight pair (wa,wb)
#define ROW4(ACC, mp, wa, wb)                             \
    ACC[0] = fma2(mp, (wa).x, ACC[0]);                    \
    ACC[1] = fma2(mp, (wa).y, ACC[1]);                    \
    ACC[2] = fma2(mp, (wb).x, ACC[2]);                    \
    ACC[3] = fma2(mp, (wb).y, ACC[3]);

// LSTM epilogue for ONE event. Accumulators passed BY VALUE (8 scalars) so
// ptxas never demotes an addressable array to local memory (the R7/R10 spill
// cause). No fence inside — caller publishes.
__device__ __forceinline__ void lstm_epi(
    u64 r0, u64 r1, u64 r2, u64 r3,
    u64 t0, u64 t1, u64 t2, u64 t3,
    int s, int d, int lane) {
    float acc0[8], acc1[8];
    {
        float2 p;
        p = unpack2(r0); acc0[0] = p.x; acc0[1] = p.y;
        p = unpack2(r1); acc0[2] = p.x; acc0[3] = p.y;
        p = unpack2(r2); acc0[4] = p.x; acc0[5] = p.y;
        p = unpack2(r3); acc0[6] = p.x; acc0[7] = p.y;
        p = unpack2(t0); acc1[0] = p.x; acc1[1] = p.y;
        p = unpack2(t1); acc1[2] = p.x; acc1[3] = p.y;
        p = unpack2(t2); acc1[4] = p.x; acc1[5] = p.y;
        p = unpack2(t3); acc1[6] = p.x; acc1[7] = p.y;
    }
    float f0g[4], o0g[4], f1g[4], o1g[4];
#pragma unroll
    for (int c2 = 0; c2 < 4; c2++) {
        f0g[c2] = __shfl_down_sync(0xffffffffu, acc0[c2], 16);
        o0g[c2] = __shfl_down_sync(0xffffffffu, acc0[4 + c2], 16);
        f1g[c2] = __shfl_down_sync(0xffffffffu, acc1[c2], 16);
        o1g[c2] = __shfl_down_sync(0xffffffffu, acc1[4 + c2], 16);
    }
    if (lane < 16) {
        float4 c0 = *(const float4*)(g_c + (size_t)s * HH + 4 * lane);
        float4 c1 = *(const float4*)(g_c + (size_t)d * HH + 4 * lane);
        float c0a[4] = {c0.x, c0.y, c0.z, c0.w};
        float c1a[4] = {c1.x, c1.y, c1.z, c1.w};
        float cn0[4], hn0[4], cn1[4], hn1[4];
#pragma unroll
        for (int c2 = 0; c2 < 4; c2++) {
            cn0[c2] = sigf(f0g[c2]) * c0a[c2] + sigf(acc0[c2]) * tanhf_(acc0[4 + c2]);
            hn0[c2] = sigf(o0g[c2]) * tanhf_(cn0[c2]);
            cn1[c2] = sigf(f1g[c2]) * c1a[c2] + sigf(acc1[c2]) * tanhf_(acc1[4 + c2]);
            hn1[c2] = sigf(o1g[c2]) * tanhf_(cn1[c2]);
        }
        if (s != d) {  // src==dst: dst (row 1) update wins, matching scatter order
            *(float4*)(g_h + (size_t)s * HH + 4 * lane) = make_float4(hn0[0], hn0[1], hn0[2], hn0[3]);
            *(float4*)(g_c + (size_t)s * HH + 4 * lane) = make_float4(cn0[0], cn0[1], cn0[2], cn0[3]);
        }
        *(float4*)(g_h + (size_t)d * HH + 4 * lane) = make_float4(hn1[0], hn1[1], hn1[2], hn1[3]);
        *(float4*)(g_c + (size_t)d * HH + 4 * lane) = make_float4(cn1[0], cn1[1], cn1[2], cn1[3]);
    }
}

// One event (DUAL=false) or two provably-independent events (DUAL=true) sharing
// every weight LDS. Split-pass LSTM; scalar-by-value epilogue; no fences inside.
template <bool DUAL>
__device__ __forceinline__ void run_events(
    int eA, int sA, int dA, int eB, int sB, int dB,
    float* sm, float* sFA, float* sFB, float* sMw, int lane,
    const float* __restrict__ eattr, const float* __restrict__ etime) {
    // ---- stage features: [0:64)=hs [64:128)=hd [128:160)=ea [160:192)=te ----
    {
        float twl = sm[OFF_TW + lane], tbl = sm[OFF_TB + lane];
        float tA = etime[eA];
        sFA[lane]       = g_h[(size_t)sA * HH + lane];
        sFA[32 + lane]  = g_h[(size_t)sA * HH + 32 + lane];
        sFA[64 + lane]  = g_h[(size_t)dA * HH + lane];
        sFA[96 + lane]  = g_h[(size_t)dA * HH + 32 + lane];
        sFA[128 + lane] = eattr[(size_t)eA * EAA + lane];
        sFA[160 + lane] = cosf(fmaf(tA, twl, tbl));
        if (DUAL) {
            float tB = etime[eB];
            sFB[lane]       = g_h[(size_t)sB * HH + lane];
            sFB[32 + lane]  = g_h[(size_t)sB * HH + 32 + lane];
            sFB[64 + lane]  = g_h[(size_t)dB * HH + lane];
            sFB[96 + lane]  = g_h[(size_t)dB * HH + 32 + lane];
            sFB[128 + lane] = eattr[(size_t)eB * EAA + lane];
            sFB[160 + lane] = cosf(fmaf(tB, twl, tbl));
        }
    }
    __syncwarp();

    // ---- message GEMV via f32x2; weights shared across up to 4 rows ----
    {
        const ulonglong2* w0p = (const ulonglong2*)(sm + OFF_WMT + lane * WMT_STRIDE);
        const ulonglong2* w1p = (const ulonglong2*)(sm + OFF_WMT + (lane + 32) * WMT_STRIDE);
        const ulonglong2* fA = (const ulonglong2*)sFA;
        const ulonglong2* fB = (const ulonglong2*)sFB;
        u64 bm0 = pack2(sm[OFF_BM + lane], 0.0f);
        u64 bm1 = pack2(sm[OFF_BM + 32 + lane], 0.0f);
        u64 a00 = bm0, a01 = bm1, a10 = bm0, a11 = bm1;
        u64 b00, b01, b10, b11;
        if (DUAL) { b00 = bm0; b01 = bm1; b10 = bm0; b11 = bm1; }
#pragma unroll 4
        for (int q = 0; q < 16; q++) {  // k[0,64): row0 -> hd, row1 -> hs
            ulonglong2 w0 = w0p[q], w1 = w1p[q];
            ulonglong2 f0 = fA[16 + q], f1 = fA[q];
            MFMA(a00, f0, w0); MFMA(a01, f0, w1);
            MFMA(a10, f1, w0); MFMA(a11, f1, w1);
            if (DUAL) {
                ulonglong2 g0 = fB[16 + q], g1 = fB[q];
                MFMA(b00, g0, w0); MFMA(b01, g0, w1);
                MFMA(b10, g1, w0); MFMA(b11, g1, w1);
            }
        }
#pragma unroll 4
        for (int q = 16; q < 32; q++) {  // k[64,128): row0 -> hs, row1 -> hd
            ulonglong2 w0 = w0p[q], w1 = w1p[q];
            ulonglong2 f0 = fA[q - 16], f1 = fA[q];
            MFMA(a00, f0, w0); MFMA(a01, f0, w1);
            MFMA(a10, f1, w0); MFMA(a11, f1, w1);
            if (DUAL) {
                ulonglong2 g0 = fB[q - 16], g1 = fB[q];
                MFMA(b00, g0, w0); MFMA(b01, g0, w1);
                MFMA(b10, g1, w0); MFMA(b11, g1, w1);
            }
        }
#pragma unroll 4
        for (int q = 32; q < 48; q++) {  // k[128,192): shared ea/te per event
            ulonglong2 w0 = w0p[q], w1 = w1p[q];
            ulonglong2 f = fA[q];
            MFMA(a00, f, w0); MFMA(a01, f, w1);
            MFMA(a10, f, w0); MFMA(a11, f, w1);
            if (DUAL) {
                ulonglong2 g = fB[q];
                MFMA(b00, g, w0); MFMA(b01, g, w1);
                MFMA(b10, g, w0); MFMA(b11, g, w1);
            }
        }
        float2 p0 = unpack2(a00), p1 = unpack2(a01), p2 = unpack2(a10), p3 = unpack2(a11);
        sMw[lane]      = fmaxf(p0.x + p0.y, 0.0f);
        sMw[32 + lane] = fmaxf(p1.x + p1.y, 0.0f);
        sMw[64 + lane] = fmaxf(p2.x + p2.y, 0.0f);
        sMw[96 + lane] = fmaxf(p3.x + p3.y, 0.0f);
        if (DUAL) {
            float2 q0 = unpack2(b00), q1 = unpack2(b01), q2 = unpack2(b10), q3 = unpack2(b11);
            sMw[128 + lane] = fmaxf(q0.x + q0.y, 0.0f);
            sMw[160 + lane] = fmaxf(q1.x + q1.y, 0.0f);
            sMw[192 + lane] = fmaxf(q2.x + q2.y, 0.0f);
            sMw[224 + lane] = fmaxf(q3.x + q3.y, 0.0f);
        }
    }
    __syncwarp();

    // ---- LSTM gates: split-pass, each weight LDS feeds up to 4 rows ----
    {
        ulonglong2 bl_lo = *(const ulonglong2*)(sm + OFF_BL + 4 * lane);
        ulonglong2 bl_hi = *(const ulonglong2*)(sm + OFF_BL + 128 + 4 * lane);
        u64 A0[4] = {bl_lo.x, bl_lo.y, bl_hi.x, bl_hi.y};  // A row0 (src)
        u64 A1[4] = {bl_lo.x, bl_lo.y, bl_hi.x, bl_hi.y};  // A row1 (dst)
        u64 B0[4], B1[4];
        if (DUAL) {
#pragma unroll
            for (int j = 0; j < 4; j++) { B0[j] = A0[j]; B1[j] = A0[j]; }
        }
        // pass 1: g += m @ W_ih  (only wa,wb live)
        {
            const ulonglong2* wih2 = (const ulonglong2*)(sm + OFF_WIH);
#pragma unroll 4
            for (int k = 0; k < 64; k++) {
                ulonglong2 wa = wih2[(k << 6) + lane], wb = wih2[(k << 6) + 32 + lane];
                float m0A = sMw[k], m1A = sMw[64 + k];
                u64 p0 = pack2(m0A, m0A), p1 = pack2(m1A, m1A);
                ROW4(A0, p0, wa, wb);
                ROW4(A1, p1, wa, wb);
                if (DUAL) {
                    float m0B = sMw[128 + k], m1B = sMw[192 + k];
                    u64 q0 = pack2(m0B, m0B), q1 = pack2(m1B, m1B);
                    ROW4(B0, q0, wa, wb);
                    ROW4(B1, q1, wa, wb);
                }
            }
        }
        // pass 2: g += h @ W_hh  (only ua,ub live)
        {
            const ulonglong2* whh2 = (const ulonglong2*)(sm + OFF_WHH);
#pragma unroll 4
            for (int k = 0; k < 64; k++) {
                ulonglong2 ua = whh2[(k << 6) + lane], ub = whh2[(k << 6) + 32 + lane];
                float h0A = sFA[k], h1A = sFA[64 + k];
                u64 p0 = pack2(h0A, h0A), p1 = pack2(h1A, h1A);
                ROW4(A0, p0, ua, ub);
                ROW4(A1, p1, ua, ub);
                if (DUAL) {
                    float h0B = sFB[k], h1B = sFB[64 + k];
                    u64 q0 = pack2(h0B, h0B), q1 = pack2(h1B, h1B);
                    ROW4(B0, q0, ua, ub);
                    ROW4(B1, q1, ua, ub);
                }
            }
        }
        lstm_epi(A0[0], A0[1], A0[2], A0[3], A1[0], A1[1], A1[2], A1[3], sA, dA, lane);
        if (DUAL)
            lstm_epi(B0[0], B0[1], B0[2], B0[3], B1[0], B1[1], B1[2], B1[3], sB, dB, lane);
    }
}

// ---- init: node-chain heads, zero touched h/c, fuse W_emb@W_cls, reset flags ----
__global__ void __launch_bounds__(512) k_init(const int* __restrict__ ei,
                                              const float* __restrict__ Wemb,
                                              const float* __restrict__ bemb,
                                              const float* __restrict__ Wcls,
                                              const float* __restrict__ bcls) {
    int t = blockIdx.x * blockDim.x + threadIdx.x;  // 65536 threads
    if (t < 2 * EE) g_head[ei[t]] = -1;
    {   // 4 threads per endpoint zero h/c (dupes benign)
        int ep = t >> 2, part = t & 3;
        if (ep < 2 * EE) {
            int v = ei[ep];
            float4 z = make_float4(0.f, 0.f, 0.f, 0.f);
            float4* hp = (float4*)(g_h + (size_t)v * HH + part * 16);
            float4* cp = (float4*)(g_c + (size_t)v * HH + part * 16);
#pragma unroll
            for (int i = 0; i < 4; i++) { hp[i] = z; cp[i] = z; }
        }
    }
    if (t < EE) g_done[t] = 0;
    if (t < 192 * AA) {
        int k = t / AA, a = t - k * AA;
        float s = 0.0f;
        const float* wr = Wemb + k * HH;
#pragma unroll 8
        for (int j = 0; j < HH; j++) s = fmaf(wr[j], Wcls[j * AA + a], s);
        g_Wc[t] = s;
    }
    if (t < AA) {
        float s = bcls[t];
        for (int j = 0; j < HH; j++) s = fmaf(bemb[j], Wcls[j * AA + t], s);
        g_bc[t] = s;
    }
    if (t == 0) { g_bar_cnt = 0u; g_bar_gen = 0u; }
}

// ---- build per-node endpoint chains (unordered) ----
__global__ void __launch_bounds__(512) k_chain(const int* __restrict__ ei) {
    int t = blockIdx.x * blockDim.x + threadIdx.x;
    if (t < 2 * EE) g_next[t] = atomicExch(&g_head[ei[t]], t);
}

// ---- per endpoint: immediate predecessor event + "has successor" flag ----
__global__ void __launch_bounds__(512) k_prevk(const int* __restrict__ ei) {
    int t = blockIdx.x * blockDim.x + threadIdx.x;
    if (t >= 2 * EE) return;
    int v = ei[t];
    int e = (t < EE) ? t : t - EE;
    int best = -1;
    int succ = 0;
    for (int j = g_head[v]; j >= 0; j = g_next[j]) {
        int ev = (j < EE) ? j : j - EE;
        if (ev < e && ev > best) best = ev;
        if (ev > e) succ = 1;
    }
    if (t < EE) { g_prev_s[e] = best; g_succ_s[e] = succ; }
    else        { g_prev_d[e] = best; g_succ_d[e] = succ; }
}

__device__ __forceinline__ void wait_preds(int p0, int p1, int p2, int p3, int lane,
                                           volatile int* vd) {
    if (lane == 0) {
        int spins = 0;
        while ((p0 >= 0 && !vd[p0]) || (p1 >= 0 && !vd[p1]) ||
               (p2 >= 0 && !vd[p2]) || (p3 >= 0 && !vd[p3])) {
            __nanosleep(40);
            if (++spins > 20000000) break;  // fail visibly, never hang
        }
    }
    __syncwarp();
}

// ---- persistent: dataflow over pairs; fuse when provably independent ----
__global__ void __launch_bounds__(NTHR, 1) k_persist(
    const float* __restrict__ x, const int* __restrict__ ei, const float* __restrict__ eattr,
    const float* __restrict__ etime, const float* __restrict__ tw, const float* __restrict__ tb,
    const float* __restrict__ Wmsg, const float* __restrict__ bmsg,
    const float* __restrict__ Wih, const float* __restrict__ Whh,
    const float* __restrict__ blstm, float* __restrict__ out) {
    extern __shared__ float sm[];
    const int tid = threadIdx.x;
    const int lane = tid & 31;
    const int wid = tid >> 5;

    // stage weights (W_msg transposed, padded stride; conflict-free LDS.128)
    for (int i = tid; i < 192 * 64; i += NTHR) {
        int k = i >> 6, j = i & 63;
        sm[OFF_WMT + j * WMT_STRIDE + k] = Wmsg[i];
    }
    {
        float4* d1 = (float4*)(sm + OFF_WIH);
        float4* d2 = (float4*)(sm + OFF_WHH);
        const float4* s1 = (const float4*)Wih;
        const float4* s2 = (const float4*)Whh;
        for (int i = tid; i < 4096; i += NTHR) { d1[i] = s1[i]; d2[i] = s2[i]; }
    }
    for (int i = tid; i < 64; i += NTHR) sm[OFF_BM + i] = bmsg[i];
    for (int i = tid; i < 256; i += NTHR) sm[OFF_BL + i] = blstm[i];
    if (tid < 32) { sm[OFF_TW + tid] = tw[tid]; sm[OFF_TB + tid] = tb[tid]; }
    __syncthreads();

    const int gw = blockIdx.x * NWARP + wid;
    float* sFA = sm + OFF_FEAT + wid * 384;
    float* sFB = sFA + 192;
    float* sMw = sm + OFF_MW + wid * 256;
    volatile int* vdone = (volatile int*)g_done;

    for (int p = gw; p < NPAIR; p += TOTWARP) {
        int eA = 2 * p, eB = 2 * p + 1;
        int sA = ei[eA], dA = ei[EE + eA];
        int sB = ei[eB], dB = ei[EE + eB];
        int pA0 = g_prev_s[eA], pA1 = g_prev_d[eA];
        int pB0 = g_prev_s[eB], pB1 = g_prev_d[eB];
        // Fusion legality: eB's dep cone lies in [0,eA) => eA not an ancestor of
        // eB AND node sets disjoint (a shared node would force a pred >= eA).
        bool fuse = (pB0 < eA) && (pB1 < eA);
        if (fuse) {
            const bool haspred = (pA0 >= 0) || (pA1 >= 0) || (pB0 >= 0) || (pB1 >= 0);
            if (haspred) {
                wait_preds(pA0, pA1, pB0, pB1, lane, vdone);
                __threadfence();  // acquire: order after flags; drop stale L1 h/c
            }
            run_events<true>(eA, sA, dA, eB, sB, dB, sm, sFA, sFB, sMw, lane, eattr, etime);
            const int succA = g_succ_s[eA] | g_succ_d[eA];
            const int succB = g_succ_s[eB] | g_succ_d[eB];
            if (succA | succB) {
                if (lane < 16) __threadfence();  // each writer publishes its stores
                __syncwarp();
                if (lane == 0) {
                    if (succA) vdone[eA] = 1;
                    if (succB) vdone[eB] = 1;
                }
            }
            __syncwarp();
        } else {
            // sequential: eB may depend on eA
            {
                const bool haspred = (pA0 >= 0) || (pA1 >= 0);
                if (haspred) {
                    wait_preds(pA0, pA1, -1, -1, lane, vdone);
                    __threadfence();
                }
                run_events<false>(eA, sA, dA, eA, sA, dA, sm, sFA, sFB, sMw, lane, eattr, etime);
                const int succA = g_succ_s[eA] | g_succ_d[eA];
                if (succA) {
                    if (lane < 16) __threadfence();
                    __syncwarp();
                    if (lane == 0) vdone[eA] = 1;
                }
                __syncwarp();
            }
            {
                const bool haspred = (pB0 >= 0) || (pB1 >= 0);
                if (haspred) {
                    wait_preds(pB0, pB1, -1, -1, lane, vdone);
                    __threadfence();
                }
                run_events<false>(eB, sB, dB, eB, sB, dB, sm, sFA, sFB, sMw, lane, eattr, etime);
                const int succB = g_succ_s[eB] | g_succ_d[eB];
                if (succB) {
                    if (lane < 16) __threadfence();
                    __syncwarp();
                    if (lane == 0) vdone[eB] = 1;
                }
                __syncwarp();
            }
        }
    }

    grid_bar();  // IVALL via tid0 drops stale L1; STG already at L2

    // ---- classifier: logits[e] = [h[dst] || x[dst]] @ Wc + bc ----
    for (int i = tid; i < 192 * AA; i += NTHR) sm[OFF_WMT + i] = g_Wc[i];
    for (int i = tid; i < AA; i += NTHR) sm[OFF_WMT + 9600 + i] = g_bc[i];
    __syncthreads();
    const float* sWc = sm + OFF_WMT;
    const float* sBc = sm + OFF_WMT + 9600;

    for (int e = gw; e < EE; e += TOTWARP) {
        int d = ei[EE + e];
        __syncwarp();
        sFA[lane]      = g_h[(size_t)d * HH + lane];
        sFA[32 + lane] = g_h[(size_t)d * HH + 32 + lane];
        {
            const float4* xv = (const float4*)(x + (size_t)d * DF);
            ((float4*)(sFA + 64))[lane] = xv[lane];
        }
        __syncwarp();
        float r0 = sBc[lane];
        float r1 = (lane < AA - 32) ? sBc[32 + lane] : 0.0f;
        const float4* fvc = (const float4*)sFA;
#pragma unroll 4
        for (int q = 0; q < 48; ++q) {
            float4 f = fvc[q];
            int kb = 4 * q;
            r0 = fmaf(f.x, sWc[(kb + 0) * AA + lane], r0);
            r0 = fmaf(f.y, sWc[(kb + 1) * AA + lane], r0);
            r0 = fmaf(f.z, sWc[(kb + 2) * AA + lane], r0);
            r0 = fmaf(f.w, sWc[(kb + 3) * AA + lane], r0);
            r1 = fmaf(f.x, sWc[(kb + 0) * AA + 32 + lane], r1);
            r1 = fmaf(f.y, sWc[(kb + 1) * AA + 32 + lane], r1);
            r1 = fmaf(f.z, sWc[(kb + 2) * AA + 32 + lane], r1);
            r1 = fmaf(f.w, sWc[(kb + 3) * AA + 32 + lane], r1);
        }
        float* op = out + (size_t)e * AA;
        op[lane] = r0;
        if (lane < AA - 32) op[32 + lane] = r1;
    }
}

extern "C" void kernel_launch(void* const* d_in, const int* in_sizes, int n_in,
                              void* d_out, int out_size) {
    const float* x     = (const float*)d_in[0];
    const int*   ei    = (const int*)d_in[1];
    const float* eattr = (const float*)d_in[2];
    const float* etime = (const float*)d_in[3];
    const float* tw    = (const float*)d_in[4];
    const float* tb    = (const float*)d_in[5];
    const float* Wmsg  = (const float*)d_in[6];
    const float* bmsg  = (const float*)d_in[7];
    const float* Wih   = (const float*)d_in[8];
    const float* Whh   = (const float*)d_in[9];
    const float* blstm = (const float*)d_in[10];
    const float* Wemb  = (const float*)d_in[11];
    const float* bemb  = (const float*)d_in[12];
    const float* Wcls  = (const float*)d_in[13];
    const float* bcls  = (const float*)d_in[14];
    float* out = (float*)d_out;

    cudaFuncSetAttribute(k_persist, cudaFuncAttributeMaxDynamicSharedMemorySize, SMEM_BYTES);

    k_init<<<128, 512>>>(ei, Wemb, bemb, Wcls, bcls);
    k_chain<<<32, 512>>>(ei);
    k_prevk<<<32, 512>>>(ei);
    k_persist<<<NBLK, NTHR, SMEM_BYTES>>>(x, ei, eattr, etime, tw, tb, Wmsg, bmsg, Wih, Whh,
                                          blstm, out);
}